// round 10
// baseline (speedup 1.0000x reference)
#include <cuda_runtime.h>
#include <math.h>

#define T_STEPS 16384
#define IDIM 1024
#define HDIM 1024
#define GDIM 4096
#define NBLK 128
#define RTHREADS 256
#define NGRP 8                          // counter shards, one 128B line each
#define CTAS_PER_GRP (NBLK / NGRP)      // 16

// ---------------- device globals (scratch; no allocations allowed) ------------
__device__ float g_xgates[(size_t)T_STEPS * GDIM];        // 256 MB input gates
// h slots: u64 { lo: value bits, hi: tag = step }, double-buffered.
__device__ __align__(16) unsigned long long g_hp[2][HDIM];
__device__ unsigned g_ctr[NGRP * 32];                     // barrier counters

// ---------------- helpers -----------------------------------------------------
static __device__ __forceinline__ unsigned long long pk2(float lo, float hi) {
    unsigned long long r;
    asm("mov.b64 %0, {%1, %2};" : "=l"(r) : "f"(lo), "f"(hi));
    return r;
}
static __device__ __forceinline__ void fma2(unsigned long long& d,
                                            unsigned long long a,
                                            unsigned long long b) {
    asm("fma.rn.f32x2 %0, %1, %2, %0;" : "+l"(d) : "l"(a), "l"(b));
}
static __device__ __forceinline__ float2 up2(unsigned long long v) {
    float2 f;
    asm("mov.b64 {%0, %1}, %2;" : "=f"(f.x), "=f"(f.y) : "l"(v));
    return f;
}
static __device__ __forceinline__ float fast_sigmoid(float x) {
    return __fdividef(1.0f, 1.0f + __expf(-x));
}
static __device__ __forceinline__ float fast_tanh(float x) {
    return 1.0f - __fdividef(2.0f, __expf(2.0f * x) + 1.0f);
}
// Morally-strong ops. relaxed = atomic, no fence cost; release = publication.
static __device__ __forceinline__ unsigned ld_rlx32(const unsigned* p) {
    unsigned v;
    asm volatile("ld.relaxed.gpu.u32 %0, [%1];" : "=r"(v) : "l"(p) : "memory");
    return v;
}
static __device__ __forceinline__ unsigned long long ld_rlx64(const unsigned long long* p) {
    unsigned long long v;
    asm volatile("ld.relaxed.gpu.b64 %0, [%1];" : "=l"(v) : "l"(p) : "memory");
    return v;
}
static __device__ __forceinline__ void st_rel64(unsigned long long* p, unsigned long long v) {
    asm volatile("st.release.gpu.b64 [%0], %1;" :: "l"(p), "l"(v) : "memory");
}
static __device__ __forceinline__ void red_rlx(unsigned* p) {
    asm volatile("red.relaxed.gpu.add.u32 [%0], %1;" :: "l"(p), "r"(1u) : "memory");
}
static __device__ __forceinline__ unsigned hi32(unsigned long long v) {
    return (unsigned)(v >> 32);
}
static __device__ __forceinline__ float lo32f(unsigned long long v) {
    return __uint_as_float((unsigned)v);
}

// ---------------- init: clear tags + counters each launch (graph replays!) ----
__global__ void init_kernel() {
    int i = threadIdx.x + blockIdx.x * blockDim.x;   // 2304 threads
    if (i < 2 * HDIM) ((unsigned long long*)g_hp)[i] = 0ULL;
    if (i < NGRP * 32) g_ctr[i] = 0u;
}

// ---------------- GEMM: x_gates = A @ W_ih^T + (b_ih + b_hh) ------------------
// (unchanged; proven R1/R5)
__global__ __launch_bounds__(256) void gemm_kernel(
    const float* __restrict__ A, const float* __restrict__ W,
    const float* __restrict__ bih, const float* __restrict__ bhh) {
    __shared__ float As[8][132];
    __shared__ float Bs[8][132];

    const int tid = threadIdx.x;
    const int m0 = blockIdx.x * 128;
    const int n0 = blockIdx.y * 128;
    const int lrow = tid >> 1;
    const int kq = (tid & 1) * 4;
    const int tm = (tid & 15) * 8;
    const int tn = (tid >> 4) * 8;

    unsigned long long acc[4][8];
#pragma unroll
    for (int i = 0; i < 4; i++)
#pragma unroll
        for (int j = 0; j < 8; j++) acc[i][j] = 0ULL;

    const float* aptr = A + (size_t)(m0 + lrow) * IDIM + kq;
    const float* wptr = W + (size_t)(n0 + lrow) * IDIM + kq;

    float4 av = *(const float4*)aptr;
    float4 bv = *(const float4*)wptr;

    for (int k0 = 0; k0 < IDIM; k0 += 8) {
        __syncthreads();
        As[kq + 0][lrow] = av.x; As[kq + 1][lrow] = av.y;
        As[kq + 2][lrow] = av.z; As[kq + 3][lrow] = av.w;
        Bs[kq + 0][lrow] = bv.x; Bs[kq + 1][lrow] = bv.y;
        Bs[kq + 2][lrow] = bv.z; Bs[kq + 3][lrow] = bv.w;
        __syncthreads();
        if (k0 + 8 < IDIM) {
            av = *(const float4*)(aptr + k0 + 8);
            bv = *(const float4*)(wptr + k0 + 8);
        }
#pragma unroll
        for (int k = 0; k < 8; k++) {
            float4 a0 = *(const float4*)&As[k][tm];
            float4 a1 = *(const float4*)&As[k][tm + 4];
            float4 b0 = *(const float4*)&Bs[k][tn];
            float4 b1 = *(const float4*)&Bs[k][tn + 4];
            unsigned long long am[4] = { pk2(a0.x, a0.y), pk2(a0.z, a0.w),
                                         pk2(a1.x, a1.y), pk2(a1.z, a1.w) };
            float bb[8] = { b0.x, b0.y, b0.z, b0.w, b1.x, b1.y, b1.z, b1.w };
#pragma unroll
            for (int j = 0; j < 8; j++) {
                unsigned long long b2 = pk2(bb[j], bb[j]);
                fma2(acc[0][j], am[0], b2);
                fma2(acc[1][j], am[1], b2);
                fma2(acc[2][j], am[2], b2);
                fma2(acc[3][j], am[3], b2);
            }
        }
    }

    float bias[8];
#pragma unroll
    for (int j = 0; j < 8; j++) bias[j] = bih[n0 + tn + j] + bhh[n0 + tn + j];

#pragma unroll
    for (int i = 0; i < 4; i++) {
        float r0v[8], r1v[8];
#pragma unroll
        for (int j = 0; j < 8; j++) {
            float2 p = up2(acc[i][j]);
            r0v[j] = p.x + bias[j];
            r1v[j] = p.y + bias[j];
        }
        size_t row0 = (size_t)(m0 + tm + 2 * i) * GDIM + n0 + tn;
        size_t row1 = row0 + GDIM;
        *(float4*)&g_xgates[row0]     = make_float4(r0v[0], r0v[1], r0v[2], r0v[3]);
        *(float4*)&g_xgates[row0 + 4] = make_float4(r0v[4], r0v[5], r0v[6], r0v[7]);
        *(float4*)&g_xgates[row1]     = make_float4(r1v[0], r1v[1], r1v[2], r1v[3]);
        *(float4*)&g_xgates[row1 + 4] = make_float4(r1v[4], r1v[5], r1v[6], r1v[7]);
    }
}

// ---------------- persistent LSTM recurrence ----------------------------------
// Hybrid sync: counters = cheap trigger (8 lines, relaxed-polled), tagged h
// slots = self-validating payload (one relaxed b64 pass after the trigger;
// tag mismatch -> rare re-poll). Publication is st.release (orders each CTA's
// step-t reads before its h(t+1) slot store and before its counter arrival),
// so the R5-proven overwrite-safety argument holds: a producer enters step
// t+1 only after ctr certifies ALL CTAs finished step t.
// Compute: warp w of CTA b owns e = b*8 + w; W_hh in regs; smem h staging;
// epilogue activations split across lanes 0..3.
__global__ __launch_bounds__(RTHREADS, 1) void lstm_kernel(const float* __restrict__ Whh) {
    __shared__ __align__(16) float sh_h[HDIM];

    const int tid = threadIdx.x;
    const int w = tid >> 5;             // warp 0..7
    const int lane = tid & 31;
    const int b = blockIdx.x;           // 0..127
    const int e = b * 8 + w;            // owned h element
    const int grp = b >> 4;             // counter shard

    unsigned long long w01[32], w23[32];
#pragma unroll
    for (int c0 = 0; c0 < 32; c0++) {
        int col = lane + 32 * c0;
        w01[c0] = pk2(Whh[(size_t)(0 * HDIM + e) * HDIM + col],
                      Whh[(size_t)(1 * HDIM + e) * HDIM + col]);
        w23[c0] = pk2(Whh[(size_t)(2 * HDIM + e) * HDIM + col],
                      Whh[(size_t)(3 * HDIM + e) * HDIM + col]);
    }

    float c_state = 0.0f;               // lane 0's value is authoritative

    // xg for step 0: lanes 0..3 hold their own gate's value.
    float xg = 0.0f;
    if (lane < 4) xg = __ldcg(&g_xgates[(size_t)0 * GDIM + lane * HDIM + e]);

    for (int t = 0; t < T_STEPS; t++) {
        if (t > 0) {
            // 1) Trigger: relaxed-poll the 8 counters (lanes 0..7).
            const unsigned target = (unsigned)t * CTAS_PER_GRP;
            int probes = 0;
            for (;;) {
                unsigned v = target;
                if (lane < NGRP) v = ld_rlx32(&g_ctr[lane * 32]);
                if (__all_sync(0xffffffffu, v >= target)) break;
                if (++probes > 1024) __nanosleep(64);
            }
            // 2) Payload: one relaxed pass over own 4 slots, tag-validated.
            const unsigned long long* hb = g_hp[t & 1];
            const unsigned wtag = (unsigned)t;
            unsigned long long v0 = ld_rlx64(hb + 2 * tid);
            unsigned long long v1 = ld_rlx64(hb + 2 * tid + 1);
            unsigned long long v2 = ld_rlx64(hb + 512 + 2 * tid);
            unsigned long long v3 = ld_rlx64(hb + 513 + 2 * tid);
            while (hi32(v0) != wtag) v0 = ld_rlx64(hb + 2 * tid);
            while (hi32(v1) != wtag) v1 = ld_rlx64(hb + 2 * tid + 1);
            while (hi32(v2) != wtag) v2 = ld_rlx64(hb + 512 + 2 * tid);
            while (hi32(v3) != wtag) v3 = ld_rlx64(hb + 513 + 2 * tid);
            sh_h[2 * tid]       = lo32f(v0);
            sh_h[2 * tid + 1]   = lo32f(v1);
            sh_h[512 + 2 * tid] = lo32f(v2);
            sh_h[513 + 2 * tid] = lo32f(v3);
        } else {
            ((float4*)sh_h)[tid] = make_float4(0.f, 0.f, 0.f, 0.f);
        }
        __syncthreads();

        unsigned long long acc01 = 0ULL, acc23 = 0ULL;
#pragma unroll
        for (int c0 = 0; c0 < 32; c0++) {
            float hv = sh_h[lane + 32 * c0];        // bank = lane: conflict-free
            unsigned long long hh = pk2(hv, hv);
            fma2(acc01, w01[c0], hh);
            fma2(acc23, w23[c0], hh);
        }
        __syncthreads();   // sh_h consumed; safe to refill next iteration

        float2 s01 = up2(acc01), s23 = up2(acc23);
#pragma unroll
        for (int off = 16; off; off >>= 1) {
            s01.x += __shfl_xor_sync(0xffffffffu, s01.x, off);
            s01.y += __shfl_xor_sync(0xffffffffu, s01.y, off);
            s23.x += __shfl_xor_sync(0xffffffffu, s23.x, off);
            s23.y += __shfl_xor_sync(0xffffffffu, s23.y, off);
        }

        // Parallel activations: lane k (0..3) computes its gate.
        float pre = (lane == 0) ? s01.x : (lane == 1) ? s01.y
                  : (lane == 2) ? s23.x : s23.y;
        float a = pre + xg;                          // xg valid on lanes 0..3
        float act = (lane == 2) ? fast_tanh(a) : fast_sigmoid(a);
        float f_ = __shfl_sync(0xffffffffu, act, 1);
        float g_ = __shfl_sync(0xffffffffu, act, 2);
        float o_ = __shfl_sync(0xffffffffu, act, 3);

        if (lane == 0) {
            c_state = f_ * c_state + act * g_;       // act = i on lane 0
            float hn = o_ * fast_tanh(c_state);
            unsigned long long pv =
                ((unsigned long long)(unsigned)(t + 1) << 32) |
                (unsigned long long)__float_as_uint(hn);
            st_rel64(&g_hp[(t + 1) & 1][e], pv);     // publish {h, tag t+1}
        }
        __syncthreads();                             // all 8 slots stored
        if (tid == 0) red_rlx(&g_ctr[grp * 32]);     // arrival (validated path)

        // Prefetch next step's xg (lanes 0..3; hides behind next poll).
        if (lane < 4 && t + 1 < T_STEPS)
            xg = __ldcg(&g_xgates[(size_t)(t + 1) * GDIM + lane * HDIM + e]);
    }
}

// ---------------- final: out = W_lin @ h_last + b_lin -------------------------
__global__ void final_kernel(const float* __restrict__ Wl,
                             const float* __restrict__ bl,
                             float* __restrict__ out) {
    __shared__ float partial[32];
    const int tid = threadIdx.x;     // 1024 threads
    // h(T) lives in buffer (T_STEPS & 1) == 0, tag T_STEPS.
    float v = Wl[tid] * lo32f(g_hp[0][tid]);
#pragma unroll
    for (int off = 16; off; off >>= 1) v += __shfl_xor_sync(0xffffffffu, v, off);
    if ((tid & 31) == 0) partial[tid >> 5] = v;
    __syncthreads();
    if (tid < 32) {
        float s = partial[tid];
#pragma unroll
        for (int off = 16; off; off >>= 1) s += __shfl_xor_sync(0xffffffffu, s, off);
        if (tid == 0) out[0] = s + bl[0];
    }
}

// ---------------- launch -------------------------------------------------------
extern "C" void kernel_launch(void* const* d_in, const int* in_sizes, int n_in,
                              void* d_out, int out_size) {
    const float* input = (const float*)d_in[0];   // [T, I]
    const float* W_ih  = (const float*)d_in[1];   // [4H, I]
    const float* W_hh  = (const float*)d_in[2];   // [4H, H]
    const float* b_ih  = (const float*)d_in[3];   // [4H]
    const float* b_hh  = (const float*)d_in[4];   // [4H]
    const float* W_lin = (const float*)d_in[5];   // [1, H]
    const float* b_lin = (const float*)d_in[6];   // [1]
    float* out = (float*)d_out;

    init_kernel<<<9, 256>>>();

    dim3 ggrid(T_STEPS / 128, GDIM / 128);        // (128, 32)
    gemm_kernel<<<ggrid, 256>>>(input, W_ih, b_ih, b_hh);

    lstm_kernel<<<NBLK, RTHREADS>>>(W_hh);

    final_kernel<<<1, 1024>>>(W_lin, b_lin, out);
}

// round 11
// speedup vs baseline: 1.5840x; 1.5840x over previous
#include <cuda_runtime.h>
#include <math.h>

#define T_STEPS 16384
#define IDIM 1024
#define HDIM 1024
#define GDIM 4096
#define NBLK 128
#define RTHREADS 256
#define NGRP 8                          // counter shards, one 128B line each
#define CTAS_PER_GRP (NBLK / NGRP)      // 16

// ---------------- device globals (scratch; no allocations allowed) ------------
__device__ float g_xgates[(size_t)T_STEPS * GDIM];   // 256 MB input gates
__device__ __align__(16) float g_h[2][HDIM];         // double-buffered hidden state
__device__ unsigned g_ctr[NGRP * 32];                // 8 counters, 128B apart

// ---------------- helpers -----------------------------------------------------
static __device__ __forceinline__ unsigned long long pk2(float lo, float hi) {
    unsigned long long r;
    asm("mov.b64 %0, {%1, %2};" : "=l"(r) : "f"(lo), "f"(hi));
    return r;
}
static __device__ __forceinline__ void fma2(unsigned long long& d,
                                            unsigned long long a,
                                            unsigned long long b) {
    asm("fma.rn.f32x2 %0, %1, %2, %0;" : "+l"(d) : "l"(a), "l"(b));
}
static __device__ __forceinline__ float2 up2(unsigned long long v) {
    float2 f;
    asm("mov.b64 {%0, %1}, %2;" : "=f"(f.x), "=f"(f.y) : "l"(v));
    return f;
}
static __device__ __forceinline__ float fast_sigmoid(float x) {
    return __fdividef(1.0f, 1.0f + __expf(-x));
}
static __device__ __forceinline__ float fast_tanh(float x) {
    return 1.0f - __fdividef(2.0f, __expf(2.0f * x) + 1.0f);
}
static __device__ __forceinline__ unsigned ld_acq(const unsigned* p) {
    unsigned v;
    asm volatile("ld.acquire.gpu.u32 %0, [%1];" : "=r"(v) : "l"(p) : "memory");
    return v;
}
static __device__ __forceinline__ void red_rel(unsigned* p) {
    asm volatile("red.release.gpu.add.u32 [%0], %1;" :: "l"(p), "r"(1u) : "memory");
}
// Shared-memory arrival counter with acq_rel semantics: the release flavor
// orders this warp's prior (global) h store before the arrival; the acquire
// flavor lets the 8th arriver pull all earlier arrivals' stores into its
// happens-before set before it issues the gpu-scope release.
static __device__ __forceinline__ unsigned atom_arrive_sh(unsigned* p) {
    unsigned old;
    unsigned addr = (unsigned)__cvta_generic_to_shared(p);
    asm volatile("atom.acq_rel.cta.shared::cta.add.u32 %0, [%1], %2;"
                 : "=r"(old) : "r"(addr), "r"(1u) : "memory");
    return old;
}

// ---------------- init: reset counters each launch (graph replays!) -----------
__global__ void init_kernel() {
    int i = threadIdx.x;
    if (i < NGRP * 32) g_ctr[i] = 0u;
}

// ---------------- GEMM: x_gates = A @ W_ih^T + (b_ih + b_hh) ------------------
// (unchanged; proven R1/R5)
__global__ __launch_bounds__(256) void gemm_kernel(
    const float* __restrict__ A, const float* __restrict__ W,
    const float* __restrict__ bih, const float* __restrict__ bhh) {
    __shared__ float As[8][132];
    __shared__ float Bs[8][132];

    const int tid = threadIdx.x;
    const int m0 = blockIdx.x * 128;
    const int n0 = blockIdx.y * 128;
    const int lrow = tid >> 1;
    const int kq = (tid & 1) * 4;
    const int tm = (tid & 15) * 8;
    const int tn = (tid >> 4) * 8;

    unsigned long long acc[4][8];
#pragma unroll
    for (int i = 0; i < 4; i++)
#pragma unroll
        for (int j = 0; j < 8; j++) acc[i][j] = 0ULL;

    const float* aptr = A + (size_t)(m0 + lrow) * IDIM + kq;
    const float* wptr = W + (size_t)(n0 + lrow) * IDIM + kq;

    float4 av = *(const float4*)aptr;
    float4 bv = *(const float4*)wptr;

    for (int k0 = 0; k0 < IDIM; k0 += 8) {
        __syncthreads();
        As[kq + 0][lrow] = av.x; As[kq + 1][lrow] = av.y;
        As[kq + 2][lrow] = av.z; As[kq + 3][lrow] = av.w;
        Bs[kq + 0][lrow] = bv.x; Bs[kq + 1][lrow] = bv.y;
        Bs[kq + 2][lrow] = bv.z; Bs[kq + 3][lrow] = bv.w;
        __syncthreads();
        if (k0 + 8 < IDIM) {
            av = *(const float4*)(aptr + k0 + 8);
            bv = *(const float4*)(wptr + k0 + 8);
        }
#pragma unroll
        for (int k = 0; k < 8; k++) {
            float4 a0 = *(const float4*)&As[k][tm];
            float4 a1 = *(const float4*)&As[k][tm + 4];
            float4 b0 = *(const float4*)&Bs[k][tn];
            float4 b1 = *(const float4*)&Bs[k][tn + 4];
            unsigned long long am[4] = { pk2(a0.x, a0.y), pk2(a0.z, a0.w),
                                         pk2(a1.x, a1.y), pk2(a1.z, a1.w) };
            float bb[8] = { b0.x, b0.y, b0.z, b0.w, b1.x, b1.y, b1.z, b1.w };
#pragma unroll
            for (int j = 0; j < 8; j++) {
                unsigned long long b2 = pk2(bb[j], bb[j]);
                fma2(acc[0][j], am[0], b2);
                fma2(acc[1][j], am[1], b2);
                fma2(acc[2][j], am[2], b2);
                fma2(acc[3][j], am[3], b2);
            }
        }
    }

    float bias[8];
#pragma unroll
    for (int j = 0; j < 8; j++) bias[j] = bih[n0 + tn + j] + bhh[n0 + tn + j];

#pragma unroll
    for (int i = 0; i < 4; i++) {
        float r0v[8], r1v[8];
#pragma unroll
        for (int j = 0; j < 8; j++) {
            float2 p = up2(acc[i][j]);
            r0v[j] = p.x + bias[j];
            r1v[j] = p.y + bias[j];
        }
        size_t row0 = (size_t)(m0 + tm + 2 * i) * GDIM + n0 + tn;
        size_t row1 = row0 + GDIM;
        *(float4*)&g_xgates[row0]     = make_float4(r0v[0], r0v[1], r0v[2], r0v[3]);
        *(float4*)&g_xgates[row0 + 4] = make_float4(r0v[4], r0v[5], r0v[6], r0v[7]);
        *(float4*)&g_xgates[row1]     = make_float4(r1v[0], r1v[1], r1v[2], r1v[3]);
        *(float4*)&g_xgates[row1 + 4] = make_float4(r1v[4], r1v[5], r1v[6], r1v[7]);
    }
}

// ---------------- persistent LSTM recurrence ----------------------------------
// R5's PROVEN protocol (8 acquire-polled counter shards, one red.release per
// CTA per step, smem h staging) with three intra-CTA cuts:
//   * xg prefetched one full step ahead (lanes 0..3, one gate each)
//   * 2 barriers/step instead of 4: post-poll (staging gate) + post-fill;
//     the post-store barrier is replaced by a smem acq_rel arrival counter
//     whose 8th arrival fires the global red.release (ordering chain:
//     st.cg -> release-atom(smem) -> acquire by trigger -> red.release.gpu)
//   * activations computed in parallel on lanes 0..3
// Overwrite safety: identical R5 argument — a CTA refills sh_h / overwrites
// g_h[t&1] only after acquiring "all CTAs finished step t", and each CTA's
// arrival is ordered after its h stores AND after its warps' reads of h(t).
__global__ __launch_bounds__(RTHREADS, 1) void lstm_kernel(const float* __restrict__ Whh) {
    __shared__ __align__(16) float sh_h[HDIM];
    __shared__ unsigned sh_arrive;      // monotone arrival counter (8 per step)

    const int tid = threadIdx.x;
    const int w = tid >> 5;             // warp 0..7
    const int lane = tid & 31;
    const int b = blockIdx.x;           // 0..127
    const int e = b * 8 + w;            // owned h element
    const int grp = b >> 4;             // counter shard

    unsigned long long w01[32], w23[32];
#pragma unroll
    for (int c0 = 0; c0 < 32; c0++) {
        int col = lane + 32 * c0;
        w01[c0] = pk2(Whh[(size_t)(0 * HDIM + e) * HDIM + col],
                      Whh[(size_t)(1 * HDIM + e) * HDIM + col]);
        w23[c0] = pk2(Whh[(size_t)(2 * HDIM + e) * HDIM + col],
                      Whh[(size_t)(3 * HDIM + e) * HDIM + col]);
    }

    if (tid == 0) sh_arrive = 0u;
    __syncthreads();

    float c_state = 0.0f;               // lane 0's value is authoritative

    // xg for step 0 (lanes 0..3: one gate each).
    float xg_cur = 0.0f, xg_next = 0.0f;
    if (lane < 4) xg_cur = __ldcg(&g_xgates[(size_t)0 * GDIM + lane * HDIM + e]);

    for (int t = 0; t < T_STEPS; t++) {
        // Prefetch NEXT step's xg before stalling (a full step to land).
        if (lane < 4 && t + 1 < T_STEPS)
            xg_next = __ldcg(&g_xgates[(size_t)(t + 1) * GDIM + lane * HDIM + e]);

        if (t > 0) {
            if (tid < NGRP) {
                const unsigned target = (unsigned)t * CTAS_PER_GRP;
                unsigned v;
                int probes = 0;
                do {
                    v = ld_acq(&g_ctr[tid * 32]);
                    if (v >= target) break;
                    if (++probes > 1024) __nanosleep(64);
                } while (true);
            }
            __syncthreads();            // (a) poll done + prior-step FMA done
            const float4* hb = (const float4*)g_h[t & 1];
            ((float4*)sh_h)[tid] = __ldcg(&hb[tid]);
        } else {
            ((float4*)sh_h)[tid] = make_float4(0.f, 0.f, 0.f, 0.f);
        }
        __syncthreads();                // (b) sh_h filled

        unsigned long long acc01 = 0ULL, acc23 = 0ULL;
#pragma unroll
        for (int c0 = 0; c0 < 32; c0++) {
            float hv = sh_h[lane + 32 * c0];        // bank = lane: conflict-free
            unsigned long long hh = pk2(hv, hv);
            fma2(acc01, w01[c0], hh);
            fma2(acc23, w23[c0], hh);
        }
        // (no barrier here: refill gated by next step's barrier (a))

        float2 s01 = up2(acc01), s23 = up2(acc23);
#pragma unroll
        for (int off = 16; off; off >>= 1) {
            s01.x += __shfl_xor_sync(0xffffffffu, s01.x, off);
            s01.y += __shfl_xor_sync(0xffffffffu, s01.y, off);
            s23.x += __shfl_xor_sync(0xffffffffu, s23.x, off);
            s23.y += __shfl_xor_sync(0xffffffffu, s23.y, off);
        }

        // Parallel activations: lane k (0..3) computes its gate.
        float pre = (lane == 0) ? s01.x : (lane == 1) ? s01.y
                  : (lane == 2) ? s23.x : s23.y;
        float a = pre + xg_cur;                      // xg_cur valid lanes 0..3
        float act = (lane == 2) ? fast_tanh(a) : fast_sigmoid(a);
        float f_ = __shfl_sync(0xffffffffu, act, 1);
        float g_ = __shfl_sync(0xffffffffu, act, 2);
        float o_ = __shfl_sync(0xffffffffu, act, 3);

        if (lane == 0) {
            c_state = f_ * c_state + act * g_;       // act = i on lane 0
            float hn = o_ * fast_tanh(c_state);
            __stcg(&g_h[(t + 1) & 1][e], hn);        // publish h(t+1)[e]
            // Warp-level arrival; 8th warp fires the CTA's global release.
            unsigned old = atom_arrive_sh(&sh_arrive);
            if (old == 8u * (unsigned)t + 7u)
                red_rel(&g_ctr[grp * 32]);
        }

        xg_cur = xg_next;
    }
}

// ---------------- final: out = W_lin @ h_last + b_lin -------------------------
__global__ void final_kernel(const float* __restrict__ Wl,
                             const float* __restrict__ bl,
                             float* __restrict__ out) {
    __shared__ float partial[32];
    const int tid = threadIdx.x;     // 1024 threads
    float v = Wl[tid] * g_h[0][tid]; // h(T) lives in buffer (T_STEPS & 1) == 0
#pragma unroll
    for (int off = 16; off; off >>= 1) v += __shfl_xor_sync(0xffffffffu, v, off);
    if ((tid & 31) == 0) partial[tid >> 5] = v;
    __syncthreads();
    if (tid < 32) {
        float s = partial[tid];
#pragma unroll
        for (int off = 16; off; off >>= 1) s += __shfl_xor_sync(0xffffffffu, s, off);
        if (tid == 0) out[0] = s + bl[0];
    }
}

// ---------------- launch -------------------------------------------------------
extern "C" void kernel_launch(void* const* d_in, const int* in_sizes, int n_in,
                              void* d_out, int out_size) {
    const float* input = (const float*)d_in[0];   // [T, I]
    const float* W_ih  = (const float*)d_in[1];   // [4H, I]
    const float* W_hh  = (const float*)d_in[2];   // [4H, H]
    const float* b_ih  = (const float*)d_in[3];   // [4H]
    const float* b_hh  = (const float*)d_in[4];   // [4H]
    const float* W_lin = (const float*)d_in[5];   // [1, H]
    const float* b_lin = (const float*)d_in[6];   // [1]
    float* out = (float*)d_out;

    init_kernel<<<1, 256>>>();

    dim3 ggrid(T_STEPS / 128, GDIM / 128);        // (128, 32)
    gemm_kernel<<<ggrid, 256>>>(input, W_ih, b_ih, b_hh);

    lstm_kernel<<<NBLK, RTHREADS>>>(W_hh);

    final_kernel<<<1, 1024>>>(W_lin, b_lin, out);
}